// round 15
// baseline (speedup 1.0000x reference)
#include <cuda_runtime.h>
#include <cuda_bf16.h>
#include <math.h>
#include <stdint.h>

// ---------------------------------------------------------------------------
// FastformerEncoderLayer  B=8 N=1024 D=1024 H=16 HD=64 FF=4096
// Round 14: occupancy push — 3-stage pipeline (60 KB) + __launch_bounds__(128,3)
// on plain GEMMs -> 3 CTAs/SM (12 warps) to cover ldmatrix/barrier latency.
// regl keeps 2 CTAs (needs 32 KB hold).
// ---------------------------------------------------------------------------

#define BATCH 8
#define SEQ   1024
#define DM    1024
#define NH    16
#define HD    64
#define FF    4096
#define ROWS  (BATCH * SEQ)          // 8192
#define KVW   (2 * DM)               // 2048

// scratch
__device__ __nv_bfloat16 g_h   [ROWS * DM];      // LN output (bf16)
__device__ __nv_bfloat16 g_kv  [ROWS * KVW];     // k|v projections (bf16)
__device__ float         g_gk  [BATCH * DM];     // global key
__device__ float         g_ps  [1024 * HD];      // gk partials: sum
__device__ float         g_pw  [1024 * HD];      // gk partials: weighted
__device__ float         g_hid2[ROWS * DM];      // hidden + attn_out (fp32)
__device__ __nv_bfloat16 g_vgk [ROWS * DM];      // v * gk (bf16)
__device__ __nv_bfloat16 g_gate[ROWS * (FF/2)];  // a * relu(g) (bf16)
// bf16 weight copies
__device__ __nv_bfloat16 g_w1[2 * DM * DM];      // kv rows of qkv_w
__device__ __nv_bfloat16 g_w2[DM * DM];
__device__ __nv_bfloat16 g_w3[FF * DM];
__device__ __nv_bfloat16 g_w4[DM * (FF/2)];

// ---------------------------------------------------------------------------
__device__ __forceinline__ uint32_t smem_u32(const void* p) {
    uint32_t a;
    asm("{ .reg .u64 t; cvta.to.shared.u64 t, %1; cvt.u32.u64 %0, t; }" : "=r"(a) : "l"(p));
    return a;
}

#define CP16(dst, src) \
    asm volatile("cp.async.cg.shared.global [%0], [%1], 16;" :: "r"(dst), "l"(src) : "memory")
#define CP_COMMIT() asm volatile("cp.async.commit_group;" ::: "memory")
#define CP_WAIT1()  asm volatile("cp.async.wait_group 1;"  ::: "memory")

#define LDMX4(d, addr)                                                        \
    asm volatile("ldmatrix.sync.aligned.m8n8.x4.shared.b16 {%0,%1,%2,%3}, [%4];" \
        : "=r"((d)[0]), "=r"((d)[1]), "=r"((d)[2]), "=r"((d)[3]) : "r"(addr))

__device__ __forceinline__ void mma16(float* d, const uint32_t* a, const uint32_t* b) {
    asm volatile(
        "mma.sync.aligned.m16n8k16.row.col.f32.bf16.bf16.f32 "
        "{%0,%1,%2,%3}, {%4,%5,%6,%7}, {%8,%9}, {%0,%1,%2,%3};"
        : "+f"(d[0]), "+f"(d[1]), "+f"(d[2]), "+f"(d[3])
        : "r"(a[0]), "r"(a[1]), "r"(a[2]), "r"(a[3]), "r"(b[0]), "r"(b[1]));
}

__inline__ __device__ float warp_sum(float v) {
    #pragma unroll
    for (int o = 16; o; o >>= 1) v += __shfl_xor_sync(0xffffffffu, v, o);
    return v;
}

// ---------------------------------------------------------------------------
// LayerNorm: 1 warp per row. grid = ROWS/8, 256 thr.
__global__ void __launch_bounds__(256)
ln_kernel(const float* __restrict__ x, const float* __restrict__ g,
          const float* __restrict__ b, __nv_bfloat16* __restrict__ y)
{
    const int wid = threadIdx.x >> 5, lane = threadIdx.x & 31;
    const size_t row = (size_t)blockIdx.x * 8 + wid;
    const float4* xr = reinterpret_cast<const float4*>(x + row * DM);

    float4 v[8];
    float s = 0.f, sq = 0.f;
    #pragma unroll
    for (int i = 0; i < 8; i++) {
        v[i] = xr[i * 32 + lane];
        s  += v[i].x + v[i].y + v[i].z + v[i].w;
        sq += v[i].x*v[i].x + v[i].y*v[i].y + v[i].z*v[i].z + v[i].w*v[i].w;
    }
    s  = warp_sum(s);
    sq = warp_sum(sq);
    const float mean = s * (1.f / DM);
    const float var  = sq * (1.f / DM) - mean * mean;
    const float rstd = rsqrtf(var + 1e-5f);

    uint2* yr = reinterpret_cast<uint2*>(y + row * DM);
    #pragma unroll
    for (int i = 0; i < 8; i++) {
        const float4 gv = reinterpret_cast<const float4*>(g)[i * 32 + lane];
        const float4 bv = reinterpret_cast<const float4*>(b)[i * 32 + lane];
        __nv_bfloat162 o01 = __floats2bfloat162_rn((v[i].x - mean) * rstd * gv.x + bv.x,
                                                   (v[i].y - mean) * rstd * gv.y + bv.y);
        __nv_bfloat162 o23 = __floats2bfloat162_rn((v[i].z - mean) * rstd * gv.z + bv.z,
                                                   (v[i].w - mean) * rstd * gv.w + bv.w);
        yr[i * 32 + lane] = make_uint2(*(uint32_t*)&o01, *(uint32_t*)&o23);
    }
}

// ---------------------------------------------------------------------------
// weight conversion, split: w1 first (kv GEMM dependency), rest second.
__global__ void __launch_bounds__(256)
cvt_w1(const float4* __restrict__ qkvw, __nv_bfloat16* __restrict__ w1)
{
    const int i = blockIdx.x * 256 + threadIdx.x;     // 262144 pairs
    const float4* src = qkvw + DM * DM / 4;
    const float4 a = src[2 * i];
    const float4 b = src[2 * i + 1];
    __nv_bfloat162 p0 = __floats2bfloat162_rn(a.x, a.y);
    __nv_bfloat162 p1 = __floats2bfloat162_rn(a.z, a.w);
    __nv_bfloat162 p2 = __floats2bfloat162_rn(b.x, b.y);
    __nv_bfloat162 p3 = __floats2bfloat162_rn(b.z, b.w);
    *reinterpret_cast<uint4*>(w1 + (size_t)i * 8) =
        make_uint4(*(uint32_t*)&p0, *(uint32_t*)&p1, *(uint32_t*)&p2, *(uint32_t*)&p3);
}

#define R1 131072                    // w2 pairs
#define R2 (R1 + 524288)             // + w3
#define R3 (R2 + 262144)             // + w4 = 917504
__global__ void __launch_bounds__(256)
cvt_rest(const float4* __restrict__ outw, const float4* __restrict__ l1w,
         const float4* __restrict__ l2w,
         __nv_bfloat16* __restrict__ w2, __nv_bfloat16* __restrict__ w3,
         __nv_bfloat16* __restrict__ w4)
{
    const int i = blockIdx.x * 256 + threadIdx.x;
    if (i >= R3) return;
    const float4* src; __nv_bfloat16* dst; int j;
    if      (i < R1) { src = outw; dst = w2; j = i; }
    else if (i < R2) { src = l1w;  dst = w3; j = i - R1; }
    else             { src = l2w;  dst = w4; j = i - R2; }
    const float4 a = src[2 * j];
    const float4 b = src[2 * j + 1];
    __nv_bfloat162 p0 = __floats2bfloat162_rn(a.x, a.y);
    __nv_bfloat162 p1 = __floats2bfloat162_rn(a.z, a.w);
    __nv_bfloat162 p2 = __floats2bfloat162_rn(b.x, b.y);
    __nv_bfloat162 p3 = __floats2bfloat162_rn(b.z, b.w);
    *reinterpret_cast<uint4*>(dst + (size_t)j * 8) =
        make_uint4(*(uint32_t*)&p0, *(uint32_t*)&p1, *(uint32_t*)&p2, *(uint32_t*)&p3);
}

// ---------------------------------------------------------------------------
// gk phase 1 (no-max; bf16 k). grid = 128 bh * 8 chunks, 256 thr.
__global__ void __launch_bounds__(256)
gk1_kernel(const __nv_bfloat16* __restrict__ kv, const float* __restrict__ kw,
           const unsigned char* __restrict__ mask,
           float* __restrict__ ps, float* __restrict__ pw)
{
    const int bh    = blockIdx.x >> 3;
    const int chunk = blockIdx.x & 7;
    const int b = bh >> 4, h = bh & 15;
    const int d   = threadIdx.x & 63;
    const int sub = threadIdx.x >> 6;            // 0..3

    const __nv_bfloat16* kbase = kv + (size_t)b * SEQ * KVW + h * HD + d;
    const float* kwr   = kw + h * SEQ;
    const unsigned char* mrow = mask + b * SEQ;

    float s0 = 0.f, w0 = 0.f, s1 = 0.f, w1 = 0.f;
    const int n0 = chunk * 128 + sub * 32;
    #pragma unroll 4
    for (int n = n0; n < n0 + 32; n += 2) {
        float ka = __bfloat162float(kbase[(size_t)n * KVW]);
        float kb = __bfloat162float(kbase[(size_t)(n + 1) * KVW]);
        float xa = mrow[n]     ? -1e9f : ka * kwr[n]     * 0.125f;
        float xb = mrow[n + 1] ? -1e9f : kb * kwr[n + 1] * 0.125f;
        float ea = __expf(xa);
        float eb = __expf(xb);
        s0 += ea; w0 += ea * ka;
        s1 += eb; w1 += eb * kb;
    }
    float s = s0 + s1, w = w0 + w1;

    __shared__ float ss[4][64], sw[4][64];
    ss[sub][d] = s; sw[sub][d] = w;
    __syncthreads();
    if (sub == 0) {
        float S = ss[0][d] + ss[1][d] + ss[2][d] + ss[3][d];
        float W = sw[0][d] + sw[1][d] + sw[2][d] + sw[3][d];
        const size_t o = (size_t)blockIdx.x * HD + d;
        ps[o] = S; pw[o] = W;
    }
}

// gk phase 2: merge 8 chunk partials + divide. grid = 128, 64 thr.
__global__ void __launch_bounds__(64)
gk2_kernel(const float* __restrict__ ps, const float* __restrict__ pw,
           float* __restrict__ gk)
{
    const int bh = blockIdx.x;
    const int d  = threadIdx.x;
    const size_t base = (size_t)bh * 8 * HD + d;
    float S = 0.f, W = 0.f;
    #pragma unroll
    for (int c = 0; c < 8; c++) { S += ps[base + c * HD]; W += pw[base + c * HD]; }
    gk[(size_t)bh * HD + d] = W / S;
}

// ---------------------------------------------------------------------------
// prep: vgk = v(bf16, kv cols 1024..2047) * gk -> bf16
__global__ void __launch_bounds__(256)
prep_vgk(const __nv_bfloat16* __restrict__ kv, const float* __restrict__ gk,
         __nv_bfloat16* __restrict__ out)
{
    const int m = blockIdx.x;
    const int t = threadIdx.x;
    const uint2 vu = *reinterpret_cast<const uint2*>(&kv[(size_t)m * KVW + DM + t * 4]);
    const float2 v01 = __bfloat1622float2(*(const __nv_bfloat162*)&vu.x);
    const float2 v23 = __bfloat1622float2(*(const __nv_bfloat162*)&vu.y);
    const float4 gv = *reinterpret_cast<const float4*>(&gk[(size_t)(m >> 10) * DM + t * 4]);
    __nv_bfloat162 o01 = __floats2bfloat162_rn(v01.x * gv.x, v01.y * gv.y);
    __nv_bfloat162 o23 = __floats2bfloat162_rn(v23.x * gv.z, v23.y * gv.w);
    *reinterpret_cast<uint2*>(&out[(size_t)m * DM + t * 4]) =
        make_uint2(*(uint32_t*)&o01, *(uint32_t*)&o23);
}

// ---------------------------------------------------------------------------
// GEMM infrastructure (persistent, flattened chunk pipeline, 3 stages)
#define NSTAGE 3
#define ROWU   20                            // uint32 per smem row (80B)
#define STG_U  (256 * ROWU)
#define STG_B  (STG_U * 4)                   // 20480 bytes
#define GEMM_SMEM (NSTAGE * STG_B)           // 60 KB -> 3 CTAs/SM
#define HOLD_U (NSTAGE * STG_U)
#define REGL_SMEM (GEMM_SMEM + 64 * 128 * 4) // 92 KB -> 2 CTAs/SM
#define GRIDP  444                           // 3 CTAs/SM * 148 SMs
#define GRIDR  296                           // 2 CTAs/SM * 148 SMs

// stage index helper: (x) mod 3 for monotonically增 chunk counters
__device__ __forceinline__ uint32_t stg3(int x) { return (uint32_t)(x % 3) * STG_B; }

// OMODE: 0 = fp32 out, 1 = bf16 out
// KSH = log2(ktiles per tile), TXSH = log2(tiles_x)
template<bool RES, int OMODE, int KSH, int TXSH>
__global__ void __launch_bounds__(128, 3)
mma_gemm_p(const __nv_bfloat16* __restrict__ A, const __nv_bfloat16* __restrict__ B,
           const float* __restrict__ bias, const float* __restrict__ res,
           void* __restrict__ Cv, int N, int lda, int ldb, int ntiles)
{
    extern __shared__ uint32_t smu[];
    const uint32_t sbase = smem_u32(smu);
    const int tid  = threadIdx.x;
    const int wid  = tid >> 5, lane = tid & 31;
    const int wm   = wid >> 1, wn = wid & 1;
    const int r    = lane >> 2, c = lane & 3;
    const int G    = gridDim.x;
    const int b0   = blockIdx.x;
    if (b0 >= ntiles) return;
    const int myTiles = (ntiles - 1 - b0) / G + 1;
    const int totc = myTiles << KSH;
    constexpr int ktm1 = (1 << KSH) - 1;
    constexpr int txm1 = (1 << TXSH) - 1;

    const int lrow = tid >> 2, lch = tid & 3;
    const uint32_t dA = sbase + (lrow * ROWU + lch * 4) * 4;
    const uint32_t dB = dA + 128 * ROWU * 4;

#define PRE(cc) do {                                                          \
        const int t_  = b0 + (((cc) >> KSH)) * G;                             \
        const int kt_ = (cc) & ktm1;                                          \
        const int nb_ = (t_ & txm1) << 7;                                     \
        const int mb_ = (t_ >> TXSH) << 7;                                    \
        const uint32_t so_ = stg3(cc);                                        \
        const __nv_bfloat16* pA = A + (size_t)(mb_ + lrow) * lda + kt_ * 32 + lch * 8; \
        const __nv_bfloat16* pB = B + (size_t)(nb_ + lrow) * ldb + kt_ * 32 + lch * 8; \
        _Pragma("unroll")                                                     \
        for (int j = 0; j < 4; j++) {                                         \
            CP16(dA + so_ + j * (32 * ROWU * 4), pA + (size_t)j * 32 * lda);  \
            CP16(dB + so_ + j * (32 * ROWU * 4), pB + (size_t)j * 32 * ldb);  \
        }                                                                     \
        CP_COMMIT();                                                          \
    } while (0)

    PRE(0); PRE(1);

    const int sub = lane >> 3, r8 = lane & 7;
    const int arow = wm * 64 + ((sub & 1) << 3) + r8;
    const uint32_t aaddr0 = sbase + (arow * ROWU + (sub >> 1) * 4) * 4;
    const int brow = wn * 64 + ((sub >> 1) << 3) + r8;
    const uint32_t baddr0 = sbase + 128 * ROWU * 4 + (brow * ROWU + (sub & 1) * 4) * 4;

    float acc[4][8][4] = {};

    for (int cc = 0; cc < totc; cc++) {
        CP_WAIT1();
        __syncthreads();
        if (cc + 2 < totc) PRE(cc + 2); else CP_COMMIT();   // keep group rhythm
        const uint32_t so = stg3(cc);

        #pragma unroll
        for (int ks = 0; ks < 2; ks++) {
            uint32_t af[4][4], bf[8][2];
            #pragma unroll
            for (int mt = 0; mt < 4; mt++)
                LDMX4(af[mt], aaddr0 + so + mt * (16 * ROWU * 4) + ks * 32);
            #pragma unroll
            for (int p = 0; p < 4; p++) {
                uint32_t t4[4];
                LDMX4(t4, baddr0 + so + p * (16 * ROWU * 4) + ks * 32);
                bf[2 * p][0] = t4[0]; bf[2 * p][1] = t4[1];
                bf[2 * p + 1][0] = t4[2]; bf[2 * p + 1][1] = t4[3];
            }
            #pragma unroll
            for (int mt = 0; mt < 4; mt++)
                #pragma unroll
                for (int nt = 0; nt < 8; nt++)
                    mma16(acc[mt][nt], af[mt], bf[nt]);
        }

        if ((cc & ktm1) == ktm1) {
            const int tile  = b0 + (cc >> KSH) * G;
            const int nbase = (tile & txm1) << 7;
            const int mbase = (tile >> TXSH) << 7;
            #pragma unroll
            for (int nt = 0; nt < 8; nt++) {
                const int col = nbase + wn * 64 + nt * 8 + 2 * c;
                const float2 bv = *reinterpret_cast<const float2*>(&bias[col]);
                #pragma unroll
                for (int mt = 0; mt < 4; mt++) {
                    const int row = mbase + wm * 64 + mt * 16 + r;
                    float2 o0, o1;
                    o0.x = acc[mt][nt][0] + bv.x; o0.y = acc[mt][nt][1] + bv.y;
                    o1.x = acc[mt][nt][2] + bv.x; o1.y = acc[mt][nt][3] + bv.y;
                    if (RES) {
                        const float2 r0 = *reinterpret_cast<const float2*>(&res[(size_t)row * N + col]);
                        const float2 r1 = *reinterpret_cast<const float2*>(&res[(size_t)(row + 8) * N + col]);
                        o0.x += r0.x; o0.y += r0.y;
                        o1.x += r1.x; o1.y += r1.y;
                    }
                    if (OMODE == 1) {
                        __nv_bfloat16* Cb = (__nv_bfloat16*)Cv;
                        __nv_bfloat162 p0 = __floats2bfloat162_rn(o0.x, o0.y);
                        __nv_bfloat162 p1 = __floats2bfloat162_rn(o1.x, o1.y);
                        *reinterpret_cast<uint32_t*>(&Cb[(size_t)row * N + col])       = *(uint32_t*)&p0;
                        *reinterpret_cast<uint32_t*>(&Cb[(size_t)(row + 8) * N + col]) = *(uint32_t*)&p1;
                    } else {
                        float* Cf = (float*)Cv;
                        *reinterpret_cast<float2*>(&Cf[(size_t)row * N + col])       = o0;
                        *reinterpret_cast<float2*>(&Cf[(size_t)(row + 8) * N + col]) = o1;
                    }
                    acc[mt][nt][0] = acc[mt][nt][1] = acc[mt][nt][2] = acc[mt][nt][3] = 0.f;
                }
            }
        }
    }
#undef PRE
}

// ---------------------------------------------------------------------------
// persistent fused ff1 + ReGLU. 64 chunks per tile (2 passes of 32), tiles_x=16.
__global__ void __launch_bounds__(128, 2)
regl_gemm_p(const __nv_bfloat16* __restrict__ A, const __nv_bfloat16* __restrict__ B,
            const float* __restrict__ bias, __nv_bfloat16* __restrict__ gate,
            int ntiles)
{
    extern __shared__ uint32_t smu[];
    const uint32_t sbase = smem_u32(smu);
    const int tid  = threadIdx.x;
    const int wid  = tid >> 5, lane = tid & 31;
    const int wm   = wid >> 1, wn = wid & 1;
    const int r    = lane >> 2, c = lane & 3;
    const int G    = gridDim.x;
    const int b0   = blockIdx.x;
    if (b0 >= ntiles) return;
    const int myTiles = (ntiles - 1 - b0) / G + 1;
    const int totc = myTiles << 6;

    const int lrow = tid >> 2, lch = tid & 3;
    const uint32_t dA = sbase + (lrow * ROWU + lch * 4) * 4;
    const uint32_t dB = dA + 128 * ROWU * 4;

#define PRE(cc) do {                                                          \
        const int t_  = b0 + (((cc) >> 6)) * G;                               \
        const int kt_ = (cc) & 63;                                            \
        const int nb_ = (t_ & 15) << 7;                                       \
        const int mb_ = (t_ >> 4) << 7;                                       \
        const int k0_ = (kt_ & 31) * 32;                                      \
        const uint32_t so_ = stg3(cc);                                        \
        const __nv_bfloat16* pA = A + (size_t)(mb_ + lrow) * DM + k0_ + lch * 8; \
        const __nv_bfloat16* pB = B + (size_t)(nb_ + lrow + ((kt_ >> 5) ? 2048 : 0)) * DM + k0_ + lch * 8; \
        _Pragma("unroll")                                                     \
        for (int j = 0; j < 4; j++) {                                         \
            CP16(dA + so_ + j * (32 * ROWU * 4), pA + (size_t)j * 32 * DM);   \
            CP16(dB + so_ + j * (32 * ROWU * 4), pB + (size_t)j * 32 * DM);   \
        }                                                                     \
        CP_COMMIT();                                                          \
    } while (0)

    PRE(0); PRE(1);

    const int sub = lane >> 3, r8 = lane & 7;
    const int arow = wm * 64 + ((sub & 1) << 3) + r8;
    const uint32_t aaddr0 = sbase + (arow * ROWU + (sub >> 1) * 4) * 4;
    const int brow = wn * 64 + ((sub >> 1) << 3) + r8;
    const uint32_t baddr0 = sbase + 128 * ROWU * 4 + (brow * ROWU + (sub & 1) * 4) * 4;

    float acc[4][8][4] = {};

    for (int cc = 0; cc < totc; cc++) {
        CP_WAIT1();
        __syncthreads();
        if (cc + 2 < totc) PRE(cc + 2); else CP_COMMIT();
        const uint32_t so = stg3(cc);

        #pragma unroll
        for (int ks = 0; ks < 2; ks++) {
            uint32_t af[4][4], bf[8][2];
            #pragma unroll
            for (int mt = 0; mt < 4; mt++)
                LDMX4(af[mt], aaddr0 + so + mt * (16 * ROWU * 4) + ks * 32);
            #pragma unroll
            for (int p = 0; p < 4; p++) {
                uint32_t t4[4];
                LDMX4(t4, baddr0 + so + p * (16 * ROWU * 4) + ks * 32);
                bf[2 * p][0] = t4[0]; bf[2 * p][1] = t4[1];
                bf[2 * p + 1][0] = t4[2]; bf[2 * p + 1][1] = t4[3];
            }
            #pragma unroll
            for (int mt = 0; mt < 4; mt++)
                #pragma unroll
                for (int nt = 0; nt < 8; nt++)
                    mma16(acc[mt][nt], af[mt], bf[nt]);
        }

        const int kt = cc & 63;
        if (kt == 31) {
            const int tile  = b0 + (cc >> 6) * G;
            const int nbase = (tile & 15) << 7;
            #pragma unroll
            for (int nt = 0; nt < 8; nt++) {
                const int col = nbase + wn * 64 + nt * 8 + 2 * c;
                const float2 bv = *reinterpret_cast<const float2*>(&bias[col]);
                #pragma unroll
                for (int mt = 0; mt < 4; mt++) {
                    __nv_bfloat162 p0 = __floats2bfloat162_rn(acc[mt][nt][0] + bv.x,
                                                              acc[mt][nt][1] + bv.y);
                    __nv_bfloat162 p1 = __floats2bfloat162_rn(acc[mt][nt][2] + bv.x,
                                                              acc[mt][nt][3] + bv.y);
                    const int slot = (nt * 4 + mt) * 2;
                    smu[HOLD_U + slot * 128 + tid]       = *(uint32_t*)&p0;
                    smu[HOLD_U + (slot + 1) * 128 + tid] = *(uint32_t*)&p1;
                    acc[mt][nt][0] = acc[mt][nt][1] = acc[mt][nt][2] = acc[mt][nt][3] = 0.f;
                }
            }
        } else if (kt == 63) {
            const int tile  = b0 + (cc >> 6) * G;
            const int nbase = (tile & 15) << 7;
            const int mbase = (tile >> 4) << 7;
            #pragma unroll
            for (int nt = 0; nt < 8; nt++) {
                const int col = nbase + wn * 64 + nt * 8 + 2 * c;
                const float2 bg = *reinterpret_cast<const float2*>(&bias[2048 + col]);
                #pragma unroll
                for (int mt = 0; mt < 4; mt++) {
                    const int row = mbase + wm * 64 + mt * 16 + r;
                    const float g0x = fmaxf(acc[mt][nt][0] + bg.x, 0.f);
                    const float g0y = fmaxf(acc[mt][nt][1] + bg.y, 0.f);
                    const float g1x = fmaxf(acc[mt][nt][2] + bg.x, 0.f);
                    const float g1y = fmaxf(acc[mt][nt][3] + bg.y, 0.f);
                    const int slot = (nt * 4 + mt) * 2;
                    const uint32_t a0 = smu[HOLD_U + slot * 128 + tid];
                    const uint32_t a1 = smu[HOLD_U + (slot + 1) * 128 + tid];
                    const float2 af0 = __bfloat1622float2(*(const __nv_bfloat162*)&a0);
                    const float2 af1 = __bfloat1622float2(*(const __nv_bfloat162*)&a1);
                    __nv_bfloat162 p0 = __floats2bfloat162_rn(af0.x * g0x, af0.y * g0y);
                    __nv_bfloat162 p1 = __floats2bfloat162_rn(af1.x * g1x, af1.y * g1y);
                    *reinterpret_cast<uint32_t*>(&gate[(size_t)row * 2048 + col])       = *(uint32_t*)&p0;
                    *reinterpret_cast<uint32_t*>(&gate[(size_t)(row + 8) * 2048 + col]) = *(uint32_t*)&p1;
                    acc[mt][nt][0] = acc[mt][nt][1] = acc[mt][nt][2] = acc[mt][nt][3] = 0.f;
                }
            }
        }
    }
#undef PRE
}

// ---------------------------------------------------------------------------
extern "C" void kernel_launch(void* const* d_in, const int* in_sizes, int n_in,
                              void* d_out, int out_size)
{
    const float*         hidden = (const float*)d_in[0];
    const unsigned char* mask   = (const unsigned char*)d_in[1];
    const float*         qkv_w  = (const float*)d_in[2];
    const float*         qkv_b  = (const float*)d_in[3];
    const float*         out_w  = (const float*)d_in[4];
    const float*         out_b  = (const float*)d_in[5];
    const float*         key_w  = (const float*)d_in[7];
    const float*         n1g    = (const float*)d_in[8];
    const float*         n1b    = (const float*)d_in[9];
    const float*         n2g    = (const float*)d_in[10];
    const float*         n2b    = (const float*)d_in[11];
    const float*         l1w    = (const float*)d_in[12];
    const float*         l1b    = (const float*)d_in[13];
    const float*         l2w    = (const float*)d_in[14];
    const float*         l2b    = (const float*)d_in[15];
    float* out = (float*)d_out;

    __nv_bfloat16 *h, *kvb, *vgk, *gate, *w1, *w2, *w3, *w4;
    float *gk, *ps, *pw, *hid2;
    cudaGetSymbolAddress((void**)&h,    g_h);
    cudaGetSymbolAddress((void**)&kvb,  g_kv);
    cudaGetSymbolAddress((void**)&gk,   g_gk);
    cudaGetSymbolAddress((void**)&ps,   g_ps);
    cudaGetSymbolAddress((void**)&pw,   g_pw);
    cudaGetSymbolAddress((void**)&hid2, g_hid2);
    cudaGetSymbolAddress((void**)&vgk,  g_vgk);
    cudaGetSymbolAddress((void**)&gate, g_gate);
    cudaGetSymbolAddress((void**)&w1,   g_w1);
    cudaGetSymbolAddress((void**)&w2,   g_w2);
    cudaGetSymbolAddress((void**)&w3,   g_w3);
    cudaGetSymbolAddress((void**)&w4,   g_w4);

    cudaFuncSetAttribute((const void*)mma_gemm_p<false,1,5,4>, cudaFuncAttributeMaxDynamicSharedMemorySize, GEMM_SMEM);
    cudaFuncSetAttribute((const void*)mma_gemm_p<true,0,5,3>,  cudaFuncAttributeMaxDynamicSharedMemorySize, GEMM_SMEM);
    cudaFuncSetAttribute((const void*)mma_gemm_p<true,0,6,3>,  cudaFuncAttributeMaxDynamicSharedMemorySize, GEMM_SMEM);
    cudaFuncSetAttribute((const void*)regl_gemm_p,             cudaFuncAttributeMaxDynamicSharedMemorySize, REGL_SMEM);

    // 1) w1 conversion (kv GEMM dependency)
    cvt_w1<<<262144 / 256, 256>>>((const float4*)qkv_w, w1);

    // 2) rest of weights
    cvt_rest<<<(R3 + 255) / 256, 256>>>((const float4*)out_w, (const float4*)l1w,
                                        (const float4*)l2w, w2, w3, w4);

    // 3) LN1
    ln_kernel<<<ROWS / 8, 256>>>(hidden, n1g, n1b, h);

    // 4) kv GEMM (persistent, bf16 out).  16x64 = 1024 tiles.  [ncu-captured]
    mma_gemm_p<false,1,5,4><<<GRIDP, 128, GEMM_SMEM>>>(
        h, w1, qkv_b + DM, nullptr, kvb, KVW, DM, DM, 1024);

    // 5) gk phase 1 (no-max, bf16 k)
    gk1_kernel<<<BATCH * NH * 8, 256>>>(kvb, key_w, mask, ps, pw);

    // 6) gk phase 2
    gk2_kernel<<<BATCH * NH, 64>>>(ps, pw, gk);

    // 7) vgk = v * gk
    prep_vgk<<<ROWS, 256>>>(kvb, gk, vgk);

    // 8) hid2 = vgk @ out_w^T + out_b + hidden.  8x64 = 512 tiles.
    mma_gemm_p<true,0,5,3><<<GRIDP, 128, GEMM_SMEM>>>(
        vgk, w2, out_b, hidden, hid2, DM, DM, DM, 512);

    // 9) LN2
    ln_kernel<<<ROWS / 8, 256>>>(hid2, n2g, n2b, h);

    // 10) gate = (h@w3a^T+ba) * relu(h@w3g^T+bg).  16x64 = 1024 tiles.
    regl_gemm_p<<<GRIDR, 128, REGL_SMEM>>>(h, w3, l1b, gate, 1024);

    // 11) out = gate @ lin2_w^T + lin2_b + hid2.  8x64 = 512 tiles, K=2048.
    mma_gemm_p<true,0,6,3><<<GRIDP, 128, GEMM_SMEM>>>(
        gate, w4, l2b, hid2, out, DM, FF / 2, FF / 2, 512);
}

// round 16
// speedup vs baseline: 1.1345x; 1.1345x over previous
#include <cuda_runtime.h>
#include <cuda_bf16.h>
#include <math.h>
#include <stdint.h>

// ---------------------------------------------------------------------------
// FastformerEncoderLayer  B=8 N=1024 D=1024 H=16 HD=64 FF=4096
// Round 16: revert occupancy experiment (2 CTAs/SM, no reg cap). Plain GEMMs
// move to BK=64 chunks (144B padded rows, 3 stages) -> half the barriers.
// regl keeps the round-13 BK=32 + smem-hold design.
// ---------------------------------------------------------------------------

#define BATCH 8
#define SEQ   1024
#define DM    1024
#define NH    16
#define HD    64
#define FF    4096
#define ROWS  (BATCH * SEQ)          // 8192
#define KVW   (2 * DM)               // 2048

// scratch
__device__ __nv_bfloat16 g_h   [ROWS * DM];      // LN output (bf16)
__device__ __nv_bfloat16 g_kv  [ROWS * KVW];     // k|v projections (bf16)
__device__ float         g_gk  [BATCH * DM];     // global key
__device__ float         g_ps  [1024 * HD];      // gk partials: sum
__device__ float         g_pw  [1024 * HD];      // gk partials: weighted
__device__ float         g_hid2[ROWS * DM];      // hidden + attn_out (fp32)
__device__ __nv_bfloat16 g_vgk [ROWS * DM];      // v * gk (bf16)
__device__ __nv_bfloat16 g_gate[ROWS * (FF/2)];  // a * relu(g) (bf16)
// bf16 weight copies
__device__ __nv_bfloat16 g_w1[2 * DM * DM];      // kv rows of qkv_w
__device__ __nv_bfloat16 g_w2[DM * DM];
__device__ __nv_bfloat16 g_w3[FF * DM];
__device__ __nv_bfloat16 g_w4[DM * (FF/2)];

// ---------------------------------------------------------------------------
__device__ __forceinline__ uint32_t smem_u32(const void* p) {
    uint32_t a;
    asm("{ .reg .u64 t; cvta.to.shared.u64 t, %1; cvt.u32.u64 %0, t; }" : "=r"(a) : "l"(p));
    return a;
}

#define CP16(dst, src) \
    asm volatile("cp.async.cg.shared.global [%0], [%1], 16;" :: "r"(dst), "l"(src) : "memory")
#define CP_COMMIT() asm volatile("cp.async.commit_group;" ::: "memory")
#define CP_WAIT1()  asm volatile("cp.async.wait_group 1;"  ::: "memory")
#define CP_WAIT2()  asm volatile("cp.async.wait_group 2;"  ::: "memory")

#define LDMX4(d, addr)                                                        \
    asm volatile("ldmatrix.sync.aligned.m8n8.x4.shared.b16 {%0,%1,%2,%3}, [%4];" \
        : "=r"((d)[0]), "=r"((d)[1]), "=r"((d)[2]), "=r"((d)[3]) : "r"(addr))

__device__ __forceinline__ void mma16(float* d, const uint32_t* a, const uint32_t* b) {
    asm volatile(
        "mma.sync.aligned.m16n8k16.row.col.f32.bf16.bf16.f32 "
        "{%0,%1,%2,%3}, {%4,%5,%6,%7}, {%8,%9}, {%0,%1,%2,%3};"
        : "+f"(d[0]), "+f"(d[1]), "+f"(d[2]), "+f"(d[3])
        : "r"(a[0]), "r"(a[1]), "r"(a[2]), "r"(a[3]), "r"(b[0]), "r"(b[1]));
}

__inline__ __device__ float warp_sum(float v) {
    #pragma unroll
    for (int o = 16; o; o >>= 1) v += __shfl_xor_sync(0xffffffffu, v, o);
    return v;
}

// ---------------------------------------------------------------------------
// LayerNorm: 1 warp per row. grid = ROWS/8, 256 thr.
__global__ void __launch_bounds__(256)
ln_kernel(const float* __restrict__ x, const float* __restrict__ g,
          const float* __restrict__ b, __nv_bfloat16* __restrict__ y)
{
    const int wid = threadIdx.x >> 5, lane = threadIdx.x & 31;
    const size_t row = (size_t)blockIdx.x * 8 + wid;
    const float4* xr = reinterpret_cast<const float4*>(x + row * DM);

    float4 v[8];
    float s = 0.f, sq = 0.f;
    #pragma unroll
    for (int i = 0; i < 8; i++) {
        v[i] = xr[i * 32 + lane];
        s  += v[i].x + v[i].y + v[i].z + v[i].w;
        sq += v[i].x*v[i].x + v[i].y*v[i].y + v[i].z*v[i].z + v[i].w*v[i].w;
    }
    s  = warp_sum(s);
    sq = warp_sum(sq);
    const float mean = s * (1.f / DM);
    const float var  = sq * (1.f / DM) - mean * mean;
    const float rstd = rsqrtf(var + 1e-5f);

    uint2* yr = reinterpret_cast<uint2*>(y + row * DM);
    #pragma unroll
    for (int i = 0; i < 8; i++) {
        const float4 gv = reinterpret_cast<const float4*>(g)[i * 32 + lane];
        const float4 bv = reinterpret_cast<const float4*>(b)[i * 32 + lane];
        __nv_bfloat162 o01 = __floats2bfloat162_rn((v[i].x - mean) * rstd * gv.x + bv.x,
                                                   (v[i].y - mean) * rstd * gv.y + bv.y);
        __nv_bfloat162 o23 = __floats2bfloat162_rn((v[i].z - mean) * rstd * gv.z + bv.z,
                                                   (v[i].w - mean) * rstd * gv.w + bv.w);
        yr[i * 32 + lane] = make_uint2(*(uint32_t*)&o01, *(uint32_t*)&o23);
    }
}

// ---------------------------------------------------------------------------
// weight conversion, split: w1 first (kv GEMM dependency), rest second.
__global__ void __launch_bounds__(256)
cvt_w1(const float4* __restrict__ qkvw, __nv_bfloat16* __restrict__ w1)
{
    const int i = blockIdx.x * 256 + threadIdx.x;     // 262144 pairs
    const float4* src = qkvw + DM * DM / 4;
    const float4 a = src[2 * i];
    const float4 b = src[2 * i + 1];
    __nv_bfloat162 p0 = __floats2bfloat162_rn(a.x, a.y);
    __nv_bfloat162 p1 = __floats2bfloat162_rn(a.z, a.w);
    __nv_bfloat162 p2 = __floats2bfloat162_rn(b.x, b.y);
    __nv_bfloat162 p3 = __floats2bfloat162_rn(b.z, b.w);
    *reinterpret_cast<uint4*>(w1 + (size_t)i * 8) =
        make_uint4(*(uint32_t*)&p0, *(uint32_t*)&p1, *(uint32_t*)&p2, *(uint32_t*)&p3);
}

#define R1 131072                    // w2 pairs
#define R2 (R1 + 524288)             // + w3
#define R3 (R2 + 262144)             // + w4 = 917504
__global__ void __launch_bounds__(256)
cvt_rest(const float4* __restrict__ outw, const float4* __restrict__ l1w,
         const float4* __restrict__ l2w,
         __nv_bfloat16* __restrict__ w2, __nv_bfloat16* __restrict__ w3,
         __nv_bfloat16* __restrict__ w4)
{
    const int i = blockIdx.x * 256 + threadIdx.x;
    if (i >= R3) return;
    const float4* src; __nv_bfloat16* dst; int j;
    if      (i < R1) { src = outw; dst = w2; j = i; }
    else if (i < R2) { src = l1w;  dst = w3; j = i - R1; }
    else             { src = l2w;  dst = w4; j = i - R2; }
    const float4 a = src[2 * j];
    const float4 b = src[2 * j + 1];
    __nv_bfloat162 p0 = __floats2bfloat162_rn(a.x, a.y);
    __nv_bfloat162 p1 = __floats2bfloat162_rn(a.z, a.w);
    __nv_bfloat162 p2 = __floats2bfloat162_rn(b.x, b.y);
    __nv_bfloat162 p3 = __floats2bfloat162_rn(b.z, b.w);
    *reinterpret_cast<uint4*>(dst + (size_t)j * 8) =
        make_uint4(*(uint32_t*)&p0, *(uint32_t*)&p1, *(uint32_t*)&p2, *(uint32_t*)&p3);
}

// ---------------------------------------------------------------------------
// gk phase 1 (no-max; bf16 k). grid = 128 bh * 8 chunks, 256 thr.
__global__ void __launch_bounds__(256)
gk1_kernel(const __nv_bfloat16* __restrict__ kv, const float* __restrict__ kw,
           const unsigned char* __restrict__ mask,
           float* __restrict__ ps, float* __restrict__ pw)
{
    const int bh    = blockIdx.x >> 3;
    const int chunk = blockIdx.x & 7;
    const int b = bh >> 4, h = bh & 15;
    const int d   = threadIdx.x & 63;
    const int sub = threadIdx.x >> 6;            // 0..3

    const __nv_bfloat16* kbase = kv + (size_t)b * SEQ * KVW + h * HD + d;
    const float* kwr   = kw + h * SEQ;
    const unsigned char* mrow = mask + b * SEQ;

    float s0 = 0.f, w0 = 0.f, s1 = 0.f, w1 = 0.f;
    const int n0 = chunk * 128 + sub * 32;
    #pragma unroll 4
    for (int n = n0; n < n0 + 32; n += 2) {
        float ka = __bfloat162float(kbase[(size_t)n * KVW]);
        float kb = __bfloat162float(kbase[(size_t)(n + 1) * KVW]);
        float xa = mrow[n]     ? -1e9f : ka * kwr[n]     * 0.125f;
        float xb = mrow[n + 1] ? -1e9f : kb * kwr[n + 1] * 0.125f;
        float ea = __expf(xa);
        float eb = __expf(xb);
        s0 += ea; w0 += ea * ka;
        s1 += eb; w1 += eb * kb;
    }
    float s = s0 + s1, w = w0 + w1;

    __shared__ float ss[4][64], sw[4][64];
    ss[sub][d] = s; sw[sub][d] = w;
    __syncthreads();
    if (sub == 0) {
        float S = ss[0][d] + ss[1][d] + ss[2][d] + ss[3][d];
        float W = sw[0][d] + sw[1][d] + sw[2][d] + sw[3][d];
        const size_t o = (size_t)blockIdx.x * HD + d;
        ps[o] = S; pw[o] = W;
    }
}

// gk phase 2: merge 8 chunk partials + divide. grid = 128, 64 thr.
__global__ void __launch_bounds__(64)
gk2_kernel(const float* __restrict__ ps, const float* __restrict__ pw,
           float* __restrict__ gk)
{
    const int bh = blockIdx.x;
    const int d  = threadIdx.x;
    const size_t base = (size_t)bh * 8 * HD + d;
    float S = 0.f, W = 0.f;
    #pragma unroll
    for (int c = 0; c < 8; c++) { S += ps[base + c * HD]; W += pw[base + c * HD]; }
    gk[(size_t)bh * HD + d] = W / S;
}

// ---------------------------------------------------------------------------
// prep: vgk = v(bf16, kv cols 1024..2047) * gk -> bf16
__global__ void __launch_bounds__(256)
prep_vgk(const __nv_bfloat16* __restrict__ kv, const float* __restrict__ gk,
         __nv_bfloat16* __restrict__ out)
{
    const int m = blockIdx.x;
    const int t = threadIdx.x;
    const uint2 vu = *reinterpret_cast<const uint2*>(&kv[(size_t)m * KVW + DM + t * 4]);
    const float2 v01 = __bfloat1622float2(*(const __nv_bfloat162*)&vu.x);
    const float2 v23 = __bfloat1622float2(*(const __nv_bfloat162*)&vu.y);
    const float4 gv = *reinterpret_cast<const float4*>(&gk[(size_t)(m >> 10) * DM + t * 4]);
    __nv_bfloat162 o01 = __floats2bfloat162_rn(v01.x * gv.x, v01.y * gv.y);
    __nv_bfloat162 o23 = __floats2bfloat162_rn(v23.x * gv.z, v23.y * gv.w);
    *reinterpret_cast<uint2*>(&out[(size_t)m * DM + t * 4]) =
        make_uint2(*(uint32_t*)&o01, *(uint32_t*)&o23);
}

// ---------------------------------------------------------------------------
// Plain GEMMs: BK=64 chunks. Row = 64 bf16 (128B) + 16B pad = 144B (36 u32).
// Conflict proof: 16B-group = (9*row+g) mod 8 = (row+g) mod 8, permutation
// over 8 consecutive rows. 3 stages x 36864B = 110.6 KB -> 2 CTAs/SM.
#define ROWU2  36
#define STG2_U (256 * ROWU2)                 // 9216 u32
#define STG2_B (STG2_U * 4)                  // 36864 bytes
#define GEMM2_SMEM (3 * STG2_B)              // 110592 bytes
#define GRIDP  296                           // 2 CTAs/SM * 148 SMs

__device__ __forceinline__ uint32_t stg3b(int x) { return (uint32_t)(x % 3) * STG2_B; }

// OMODE: 0 = fp32 out, 1 = bf16 out
// KSH = log2(chunks of 64 per tile), TXSH = log2(tiles_x)
template<bool RES, int OMODE, int KSH, int TXSH>
__global__ void __launch_bounds__(128, 2)
mma_gemm_p(const __nv_bfloat16* __restrict__ A, const __nv_bfloat16* __restrict__ B,
           const float* __restrict__ bias, const float* __restrict__ res,
           void* __restrict__ Cv, int N, int lda, int ldb, int ntiles)
{
    extern __shared__ uint32_t smu[];
    const uint32_t sbase = smem_u32(smu);
    const int tid  = threadIdx.x;
    const int wid  = tid >> 5, lane = tid & 31;
    const int wm   = wid >> 1, wn = wid & 1;
    const int r    = lane >> 2, c = lane & 3;
    const int G    = gridDim.x;
    const int b0   = blockIdx.x;
    if (b0 >= ntiles) return;
    const int myTiles = (ntiles - 1 - b0) / G + 1;
    const int totc = myTiles << KSH;
    constexpr int ktm1 = (1 << KSH) - 1;
    constexpr int txm1 = (1 << TXSH) - 1;

    // cp.async: ch = tid&7 (16B chunk), base row = tid>>3; 16 iters cover
    // rows 0..255 (0-127 = A, 128-255 = B).
    const int lch  = tid & 7;
    const int rbas = tid >> 3;
    const uint32_t dst0 = sbase + ((rbas * ROWU2 + lch * 4) * 4);

#define PRE(cc) do {                                                          \
        const int t_  = b0 + (((cc) >> KSH)) * G;                             \
        const int k0_ = ((cc) & ktm1) * 64 + lch * 8;                         \
        const int nb_ = (t_ & txm1) << 7;                                     \
        const int mb_ = (t_ >> TXSH) << 7;                                    \
        const uint32_t so_ = stg3b(cc);                                       \
        const __nv_bfloat16* pA = A + (size_t)(mb_ + rbas) * lda + k0_;       \
        const __nv_bfloat16* pB = B + (size_t)(nb_ + rbas) * ldb + k0_;       \
        _Pragma("unroll")                                                     \
        for (int j = 0; j < 8; j++)                                           \
            CP16(dst0 + so_ + j * (16 * ROWU2 * 4), pA + (size_t)j * 16 * lda); \
        _Pragma("unroll")                                                     \
        for (int j = 0; j < 8; j++)                                           \
            CP16(dst0 + so_ + (128 * ROWU2 * 4) + j * (16 * ROWU2 * 4),       \
                 pB + (size_t)j * 16 * ldb);                                  \
        CP_COMMIT();                                                          \
    } while (0)

    PRE(0); PRE(1);

    const int sub = lane >> 3, r8 = lane & 7;
    const int arow = wm * 64 + ((sub & 1) << 3) + r8;
    const uint32_t aaddr0 = sbase + (arow * ROWU2 + (sub >> 1) * 4) * 4;
    const int brow = wn * 64 + ((sub >> 1) << 3) + r8;
    const uint32_t baddr0 = sbase + 128 * ROWU2 * 4 + (brow * ROWU2 + (sub & 1) * 4) * 4;

    float acc[4][8][4] = {};

    for (int cc = 0; cc < totc; cc++) {
        CP_WAIT1();
        __syncthreads();
        if (cc + 2 < totc) PRE(cc + 2); else CP_COMMIT();
        const uint32_t so = stg3b(cc);

        #pragma unroll
        for (int ks = 0; ks < 4; ks++) {                 // four k16 steps
            uint32_t af[4][4], bf[8][2];
            #pragma unroll
            for (int mt = 0; mt < 4; mt++)
                LDMX4(af[mt], aaddr0 + so + mt * (16 * ROWU2 * 4) + ks * 32);
            #pragma unroll
            for (int p = 0; p < 4; p++) {
                uint32_t t4[4];
                LDMX4(t4, baddr0 + so + p * (16 * ROWU2 * 4) + ks * 32);
                bf[2 * p][0] = t4[0]; bf[2 * p][1] = t4[1];
                bf[2 * p + 1][0] = t4[2]; bf[2 * p + 1][1] = t4[3];
            }
            #pragma unroll
            for (int mt = 0; mt < 4; mt++)
                #pragma unroll
                for (int nt = 0; nt < 8; nt++)
                    mma16(acc[mt][nt], af[mt], bf[nt]);
        }

        if ((cc & ktm1) == ktm1) {
            const int tile  = b0 + (cc >> KSH) * G;
            const int nbase = (tile & txm1) << 7;
            const int mbase = (tile >> TXSH) << 7;
            #pragma unroll
            for (int nt = 0; nt < 8; nt++) {
                const int col = nbase + wn * 64 + nt * 8 + 2 * c;
                const float2 bv = *reinterpret_cast<const float2*>(&bias[col]);
                #pragma unroll
                for (int mt = 0; mt < 4; mt++) {
                    const int row = mbase + wm * 64 + mt * 16 + r;
                    float2 o0, o1;
                    o0.x = acc[mt][nt][0] + bv.x; o0.y = acc[mt][nt][1] + bv.y;
                    o1.x = acc[mt][nt][2] + bv.x; o1.y = acc[mt][nt][3] + bv.y;
                    if (RES) {
                        const float2 r0 = *reinterpret_cast<const float2*>(&res[(size_t)row * N + col]);
                        const float2 r1 = *reinterpret_cast<const float2*>(&res[(size_t)(row + 8) * N + col]);
                        o0.x += r0.x; o0.y += r0.y;
                        o1.x += r1.x; o1.y += r1.y;
                    }
                    if (OMODE == 1) {
                        __nv_bfloat16* Cb = (__nv_bfloat16*)Cv;
                        __nv_bfloat162 p0 = __floats2bfloat162_rn(o0.x, o0.y);
                        __nv_bfloat162 p1 = __floats2bfloat162_rn(o1.x, o1.y);
                        *reinterpret_cast<uint32_t*>(&Cb[(size_t)row * N + col])       = *(uint32_t*)&p0;
                        *reinterpret_cast<uint32_t*>(&Cb[(size_t)(row + 8) * N + col]) = *(uint32_t*)&p1;
                    } else {
                        float* Cf = (float*)Cv;
                        *reinterpret_cast<float2*>(&Cf[(size_t)row * N + col])       = o0;
                        *reinterpret_cast<float2*>(&Cf[(size_t)(row + 8) * N + col]) = o1;
                    }
                    acc[mt][nt][0] = acc[mt][nt][1] = acc[mt][nt][2] = acc[mt][nt][3] = 0.f;
                }
            }
        }
    }
#undef PRE
}

// ---------------------------------------------------------------------------
// regl (round-13 verbatim): BK=32, 4 stages + 32 KB hold, 2 CTAs/SM.
#define NSTAGE 4
#define ROWU   20
#define STG_U  (256 * ROWU)
#define STG_B  (STG_U * 4)                   // 20480 bytes
#define GEMM_SMEM (NSTAGE * STG_B)           // 80 KB
#define HOLD_U (NSTAGE * STG_U)
#define REGL_SMEM (GEMM_SMEM + 64 * 128 * 4) // 112 KB

__global__ void __launch_bounds__(128, 2)
regl_gemm_p(const __nv_bfloat16* __restrict__ A, const __nv_bfloat16* __restrict__ B,
            const float* __restrict__ bias, __nv_bfloat16* __restrict__ gate,
            int ntiles)
{
    extern __shared__ uint32_t smu[];
    const uint32_t sbase = smem_u32(smu);
    const int tid  = threadIdx.x;
    const int wid  = tid >> 5, lane = tid & 31;
    const int wm   = wid >> 1, wn = wid & 1;
    const int r    = lane >> 2, c = lane & 3;
    const int G    = gridDim.x;
    const int b0   = blockIdx.x;
    if (b0 >= ntiles) return;
    const int myTiles = (ntiles - 1 - b0) / G + 1;
    const int totc = myTiles << 6;

    const int lrow = tid >> 2, lch = tid & 3;
    const uint32_t dA = sbase + (lrow * ROWU + lch * 4) * 4;
    const uint32_t dB = dA + 128 * ROWU * 4;

#define PRE(cc) do {                                                          \
        const int t_  = b0 + (((cc) >> 6)) * G;                               \
        const int kt_ = (cc) & 63;                                            \
        const int nb_ = (t_ & 15) << 7;                                       \
        const int mb_ = (t_ >> 4) << 7;                                       \
        const int k0_ = (kt_ & 31) * 32;                                      \
        const uint32_t so_ = ((cc) & 3) * STG_B;                              \
        const __nv_bfloat16* pA = A + (size_t)(mb_ + lrow) * DM + k0_ + lch * 8; \
        const __nv_bfloat16* pB = B + (size_t)(nb_ + lrow + ((kt_ >> 5) ? 2048 : 0)) * DM + k0_ + lch * 8; \
        _Pragma("unroll")                                                     \
        for (int j = 0; j < 4; j++) {                                         \
            CP16(dA + so_ + j * (32 * ROWU * 4), pA + (size_t)j * 32 * DM);   \
            CP16(dB + so_ + j * (32 * ROWU * 4), pB + (size_t)j * 32 * DM);   \
        }                                                                     \
        CP_COMMIT();                                                          \
    } while (0)

    PRE(0); PRE(1); PRE(2);

    const int sub = lane >> 3, r8 = lane & 7;
    const int arow = wm * 64 + ((sub & 1) << 3) + r8;
    const uint32_t aaddr0 = sbase + (arow * ROWU + (sub >> 1) * 4) * 4;
    const int brow = wn * 64 + ((sub >> 1) << 3) + r8;
    const uint32_t baddr0 = sbase + 128 * ROWU * 4 + (brow * ROWU + (sub & 1) * 4) * 4;

    float acc[4][8][4] = {};

    for (int cc = 0; cc < totc; cc++) {
        CP_WAIT2();
        __syncthreads();
        if (cc + 3 < totc) PRE(cc + 3); else CP_COMMIT();
        const uint32_t so = (cc & 3) * STG_B;

        #pragma unroll
        for (int ks = 0; ks < 2; ks++) {
            uint32_t af[4][4], bf[8][2];
            #pragma unroll
            for (int mt = 0; mt < 4; mt++)
                LDMX4(af[mt], aaddr0 + so + mt * (16 * ROWU * 4) + ks * 32);
            #pragma unroll
            for (int p = 0; p < 4; p++) {
                uint32_t t4[4];
                LDMX4(t4, baddr0 + so + p * (16 * ROWU * 4) + ks * 32);
                bf[2 * p][0] = t4[0]; bf[2 * p][1] = t4[1];
                bf[2 * p + 1][0] = t4[2]; bf[2 * p + 1][1] = t4[3];
            }
            #pragma unroll
            for (int mt = 0; mt < 4; mt++)
                #pragma unroll
                for (int nt = 0; nt < 8; nt++)
                    mma16(acc[mt][nt], af[mt], bf[nt]);
        }

        const int kt = cc & 63;
        if (kt == 31) {
            const int tile  = b0 + (cc >> 6) * G;
            const int nbase = (tile & 15) << 7;
            #pragma unroll
            for (int nt = 0; nt < 8; nt++) {
                const int col = nbase + wn * 64 + nt * 8 + 2 * c;
                const float2 bv = *reinterpret_cast<const float2*>(&bias[col]);
                #pragma unroll
                for (int mt = 0; mt < 4; mt++) {
                    __nv_bfloat162 p0 = __floats2bfloat162_rn(acc[mt][nt][0] + bv.x,
                                                              acc[mt][nt][1] + bv.y);
                    __nv_bfloat162 p1 = __floats2bfloat162_rn(acc[mt][nt][2] + bv.x,
                                                              acc[mt][nt][3] + bv.y);
                    const int slot = (nt * 4 + mt) * 2;
                    smu[HOLD_U + slot * 128 + tid]       = *(uint32_t*)&p0;
                    smu[HOLD_U + (slot + 1) * 128 + tid] = *(uint32_t*)&p1;
                    acc[mt][nt][0] = acc[mt][nt][1] = acc[mt][nt][2] = acc[mt][nt][3] = 0.f;
                }
            }
        } else if (kt == 63) {
            const int tile  = b0 + (cc >> 6) * G;
            const int nbase = (tile & 15) << 7;
            const int mbase = (tile >> 4) << 7;
            #pragma unroll
            for (int nt = 0; nt < 8; nt++) {
                const int col = nbase + wn * 64 + nt * 8 + 2 * c;
                const float2 bg = *reinterpret_cast<const float2*>(&bias[2048 + col]);
                #pragma unroll
                for (int mt = 0; mt < 4; mt++) {
                    const int row = mbase + wm * 64 + mt * 16 + r;
                    const float g0x = fmaxf(acc[mt][nt][0] + bg.x, 0.f);
                    const float g0y = fmaxf(acc[mt][nt][1] + bg.y, 0.f);
                    const float g1x = fmaxf(acc[mt][nt][2] + bg.x, 0.f);
                    const float g1y = fmaxf(acc[mt][nt][3] + bg.y, 0.f);
                    const int slot = (nt * 4 + mt) * 2;
                    const uint32_t a0 = smu[HOLD_U + slot * 128 + tid];
                    const uint32_t a1 = smu[HOLD_U + (slot + 1) * 128 + tid];
                    const float2 af0 = __bfloat1622float2(*(const __nv_bfloat162*)&a0);
                    const float2 af1 = __bfloat1622float2(*(const __nv_bfloat162*)&a1);
                    __nv_bfloat162 p0 = __floats2bfloat162_rn(af0.x * g0x, af0.y * g0y);
                    __nv_bfloat162 p1 = __floats2bfloat162_rn(af1.x * g1x, af1.y * g1y);
                    *reinterpret_cast<uint32_t*>(&gate[(size_t)row * 2048 + col])       = *(uint32_t*)&p0;
                    *reinterpret_cast<uint32_t*>(&gate[(size_t)(row + 8) * 2048 + col]) = *(uint32_t*)&p1;
                    acc[mt][nt][0] = acc[mt][nt][1] = acc[mt][nt][2] = acc[mt][nt][3] = 0.f;
                }
            }
        }
    }
#undef PRE
}

// ---------------------------------------------------------------------------
extern "C" void kernel_launch(void* const* d_in, const int* in_sizes, int n_in,
                              void* d_out, int out_size)
{
    const float*         hidden = (const float*)d_in[0];
    const unsigned char* mask   = (const unsigned char*)d_in[1];
    const float*         qkv_w  = (const float*)d_in[2];
    const float*         qkv_b  = (const float*)d_in[3];
    const float*         out_w  = (const float*)d_in[4];
    const float*         out_b  = (const float*)d_in[5];
    const float*         key_w  = (const float*)d_in[7];
    const float*         n1g    = (const float*)d_in[8];
    const float*         n1b    = (const float*)d_in[9];
    const float*         n2g    = (const float*)d_in[10];
    const float*         n2b    = (const float*)d_in[11];
    const float*         l1w    = (const float*)d_in[12];
    const float*         l1b    = (const float*)d_in[13];
    const float*         l2w    = (const float*)d_in[14];
    const float*         l2b    = (const float*)d_in[15];
    float* out = (float*)d_out;

    __nv_bfloat16 *h, *kvb, *vgk, *gate, *w1, *w2, *w3, *w4;
    float *gk, *ps, *pw, *hid2;
    cudaGetSymbolAddress((void**)&h,    g_h);
    cudaGetSymbolAddress((void**)&kvb,  g_kv);
    cudaGetSymbolAddress((void**)&gk,   g_gk);
    cudaGetSymbolAddress((void**)&ps,   g_ps);
    cudaGetSymbolAddress((void**)&pw,   g_pw);
    cudaGetSymbolAddress((void**)&hid2, g_hid2);
    cudaGetSymbolAddress((void**)&vgk,  g_vgk);
    cudaGetSymbolAddress((void**)&gate, g_gate);
    cudaGetSymbolAddress((void**)&w1,   g_w1);
    cudaGetSymbolAddress((void**)&w2,   g_w2);
    cudaGetSymbolAddress((void**)&w3,   g_w3);
    cudaGetSymbolAddress((void**)&w4,   g_w4);

    cudaFuncSetAttribute((const void*)mma_gemm_p<false,1,4,4>, cudaFuncAttributeMaxDynamicSharedMemorySize, GEMM2_SMEM);
    cudaFuncSetAttribute((const void*)mma_gemm_p<true,0,4,3>,  cudaFuncAttributeMaxDynamicSharedMemorySize, GEMM2_SMEM);
    cudaFuncSetAttribute((const void*)mma_gemm_p<true,0,5,3>,  cudaFuncAttributeMaxDynamicSharedMemorySize, GEMM2_SMEM);
    cudaFuncSetAttribute((const void*)regl_gemm_p,             cudaFuncAttributeMaxDynamicSharedMemorySize, REGL_SMEM);

    // 1) w1 conversion (kv GEMM dependency)
    cvt_w1<<<262144 / 256, 256>>>((const float4*)qkv_w, w1);

    // 2) rest of weights
    cvt_rest<<<(R3 + 255) / 256, 256>>>((const float4*)out_w, (const float4*)l1w,
                                        (const float4*)l2w, w2, w3, w4);

    // 3) LN1
    ln_kernel<<<ROWS / 8, 256>>>(hidden, n1g, n1b, h);

    // 4) kv GEMM (bf16 out). 1024 tiles, 16 chunks of K=64.  [ncu-captured]
    mma_gemm_p<false,1,4,4><<<GRIDP, 128, GEMM2_SMEM>>>(
        h, w1, qkv_b + DM, nullptr, kvb, KVW, DM, DM, 1024);

    // 5) gk phase 1 (no-max, bf16 k)
    gk1_kernel<<<BATCH * NH * 8, 256>>>(kvb, key_w, mask, ps, pw);

    // 6) gk phase 2
    gk2_kernel<<<BATCH * NH, 64>>>(ps, pw, gk);

    // 7) vgk = v * gk
    prep_vgk<<<ROWS, 256>>>(kvb, gk, vgk);

    // 8) hid2 = vgk @ out_w^T + out_b + hidden. 512 tiles, 16 chunks.
    mma_gemm_p<true,0,4,3><<<GRIDP, 128, GEMM2_SMEM>>>(
        vgk, w2, out_b, hidden, hid2, DM, DM, DM, 512);

    // 9) LN2
    ln_kernel<<<ROWS / 8, 256>>>(hid2, n2g, n2b, h);

    // 10) gate = (h@w3a^T+ba) * relu(h@w3g^T+bg). 1024 tiles (BK=32 path).
    regl_gemm_p<<<GRIDP, 128, REGL_SMEM>>>(h, w3, l1b, gate, 1024);

    // 11) out = gate @ lin2_w^T + lin2_b + hid2. 512 tiles, 32 chunks, K=2048.
    mma_gemm_p<true,0,5,3><<<GRIDP, 128, GEMM2_SMEM>>>(
        gate, w4, l2b, hid2, out, DM, FF / 2, FF / 2, 512);
}

// round 17
// speedup vs baseline: 1.1511x; 1.0146x over previous
#include <cuda_runtime.h>
#include <cuda_bf16.h>
#include <math.h>
#include <stdint.h>

// ---------------------------------------------------------------------------
// FastformerEncoderLayer  B=8 N=1024 D=1024 H=16 HD=64 FF=4096
// Round 17: revert to round-13 (best, 506us) + 5-stage pipeline on the plain
// GEMMs (uses idle smem; depth-4 prefetch, wait_group 3). regl unchanged.
// ---------------------------------------------------------------------------

#define BATCH 8
#define SEQ   1024
#define DM    1024
#define NH    16
#define HD    64
#define FF    4096
#define ROWS  (BATCH * SEQ)          // 8192
#define KVW   (2 * DM)               // 2048

// scratch
__device__ __nv_bfloat16 g_h   [ROWS * DM];      // LN output (bf16)
__device__ __nv_bfloat16 g_kv  [ROWS * KVW];     // k|v projections (bf16)
__device__ float         g_gk  [BATCH * DM];     // global key
__device__ float         g_ps  [1024 * HD];      // gk partials: sum
__device__ float         g_pw  [1024 * HD];      // gk partials: weighted
__device__ float         g_hid2[ROWS * DM];      // hidden + attn_out (fp32)
__device__ __nv_bfloat16 g_vgk [ROWS * DM];      // v * gk (bf16)
__device__ __nv_bfloat16 g_gate[ROWS * (FF/2)];  // a * relu(g) (bf16)
// bf16 weight copies
__device__ __nv_bfloat16 g_w1[2 * DM * DM];      // kv rows of qkv_w
__device__ __nv_bfloat16 g_w2[DM * DM];
__device__ __nv_bfloat16 g_w3[FF * DM];
__device__ __nv_bfloat16 g_w4[DM * (FF/2)];

// ---------------------------------------------------------------------------
__device__ __forceinline__ uint32_t smem_u32(const void* p) {
    uint32_t a;
    asm("{ .reg .u64 t; cvta.to.shared.u64 t, %1; cvt.u32.u64 %0, t; }" : "=r"(a) : "l"(p));
    return a;
}

#define CP16(dst, src) \
    asm volatile("cp.async.cg.shared.global [%0], [%1], 16;" :: "r"(dst), "l"(src) : "memory")
#define CP_COMMIT() asm volatile("cp.async.commit_group;" ::: "memory")
#define CP_WAIT2()  asm volatile("cp.async.wait_group 2;"  ::: "memory")
#define CP_WAIT3()  asm volatile("cp.async.wait_group 3;"  ::: "memory")

#define LDMX4(d, addr)                                                        \
    asm volatile("ldmatrix.sync.aligned.m8n8.x4.shared.b16 {%0,%1,%2,%3}, [%4];" \
        : "=r"((d)[0]), "=r"((d)[1]), "=r"((d)[2]), "=r"((d)[3]) : "r"(addr))

__device__ __forceinline__ void mma16(float* d, const uint32_t* a, const uint32_t* b) {
    asm volatile(
        "mma.sync.aligned.m16n8k16.row.col.f32.bf16.bf16.f32 "
        "{%0,%1,%2,%3}, {%4,%5,%6,%7}, {%8,%9}, {%0,%1,%2,%3};"
        : "+f"(d[0]), "+f"(d[1]), "+f"(d[2]), "+f"(d[3])
        : "r"(a[0]), "r"(a[1]), "r"(a[2]), "r"(a[3]), "r"(b[0]), "r"(b[1]));
}

__inline__ __device__ float warp_sum(float v) {
    #pragma unroll
    for (int o = 16; o; o >>= 1) v += __shfl_xor_sync(0xffffffffu, v, o);
    return v;
}

// ---------------------------------------------------------------------------
// LayerNorm: 1 warp per row. grid = ROWS/8, 256 thr.
__global__ void __launch_bounds__(256)
ln_kernel(const float* __restrict__ x, const float* __restrict__ g,
          const float* __restrict__ b, __nv_bfloat16* __restrict__ y)
{
    const int wid = threadIdx.x >> 5, lane = threadIdx.x & 31;
    const size_t row = (size_t)blockIdx.x * 8 + wid;
    const float4* xr = reinterpret_cast<const float4*>(x + row * DM);

    float4 v[8];
    float s = 0.f, sq = 0.f;
    #pragma unroll
    for (int i = 0; i < 8; i++) {
        v[i] = xr[i * 32 + lane];
        s  += v[i].x + v[i].y + v[i].z + v[i].w;
        sq += v[i].x*v[i].x + v[i].y*v[i].y + v[i].z*v[i].z + v[i].w*v[i].w;
    }
    s  = warp_sum(s);
    sq = warp_sum(sq);
    const float mean = s * (1.f / DM);
    const float var  = sq * (1.f / DM) - mean * mean;
    const float rstd = rsqrtf(var + 1e-5f);

    uint2* yr = reinterpret_cast<uint2*>(y + row * DM);
    #pragma unroll
    for (int i = 0; i < 8; i++) {
        const float4 gv = reinterpret_cast<const float4*>(g)[i * 32 + lane];
        const float4 bv = reinterpret_cast<const float4*>(b)[i * 32 + lane];
        __nv_bfloat162 o01 = __floats2bfloat162_rn((v[i].x - mean) * rstd * gv.x + bv.x,
                                                   (v[i].y - mean) * rstd * gv.y + bv.y);
        __nv_bfloat162 o23 = __floats2bfloat162_rn((v[i].z - mean) * rstd * gv.z + bv.z,
                                                   (v[i].w - mean) * rstd * gv.w + bv.w);
        yr[i * 32 + lane] = make_uint2(*(uint32_t*)&o01, *(uint32_t*)&o23);
    }
}

// ---------------------------------------------------------------------------
// weight conversion, split: w1 first (kv GEMM dependency), rest second.
__global__ void __launch_bounds__(256)
cvt_w1(const float4* __restrict__ qkvw, __nv_bfloat16* __restrict__ w1)
{
    const int i = blockIdx.x * 256 + threadIdx.x;     // 262144 pairs
    const float4* src = qkvw + DM * DM / 4;
    const float4 a = src[2 * i];
    const float4 b = src[2 * i + 1];
    __nv_bfloat162 p0 = __floats2bfloat162_rn(a.x, a.y);
    __nv_bfloat162 p1 = __floats2bfloat162_rn(a.z, a.w);
    __nv_bfloat162 p2 = __floats2bfloat162_rn(b.x, b.y);
    __nv_bfloat162 p3 = __floats2bfloat162_rn(b.z, b.w);
    *reinterpret_cast<uint4*>(w1 + (size_t)i * 8) =
        make_uint4(*(uint32_t*)&p0, *(uint32_t*)&p1, *(uint32_t*)&p2, *(uint32_t*)&p3);
}

#define R1 131072                    // w2 pairs
#define R2 (R1 + 524288)             // + w3
#define R3 (R2 + 262144)             // + w4 = 917504
__global__ void __launch_bounds__(256)
cvt_rest(const float4* __restrict__ outw, const float4* __restrict__ l1w,
         const float4* __restrict__ l2w,
         __nv_bfloat16* __restrict__ w2, __nv_bfloat16* __restrict__ w3,
         __nv_bfloat16* __restrict__ w4)
{
    const int i = blockIdx.x * 256 + threadIdx.x;
    if (i >= R3) return;
    const float4* src; __nv_bfloat16* dst; int j;
    if      (i < R1) { src = outw; dst = w2; j = i; }
    else if (i < R2) { src = l1w;  dst = w3; j = i - R1; }
    else             { src = l2w;  dst = w4; j = i - R2; }
    const float4 a = src[2 * j];
    const float4 b = src[2 * j + 1];
    __nv_bfloat162 p0 = __floats2bfloat162_rn(a.x, a.y);
    __nv_bfloat162 p1 = __floats2bfloat162_rn(a.z, a.w);
    __nv_bfloat162 p2 = __floats2bfloat162_rn(b.x, b.y);
    __nv_bfloat162 p3 = __floats2bfloat162_rn(b.z, b.w);
    *reinterpret_cast<uint4*>(dst + (size_t)j * 8) =
        make_uint4(*(uint32_t*)&p0, *(uint32_t*)&p1, *(uint32_t*)&p2, *(uint32_t*)&p3);
}

// ---------------------------------------------------------------------------
// gk phase 1 (no-max; bf16 k). grid = 128 bh * 8 chunks, 256 thr.
__global__ void __launch_bounds__(256)
gk1_kernel(const __nv_bfloat16* __restrict__ kv, const float* __restrict__ kw,
           const unsigned char* __restrict__ mask,
           float* __restrict__ ps, float* __restrict__ pw)
{
    const int bh    = blockIdx.x >> 3;
    const int chunk = blockIdx.x & 7;
    const int b = bh >> 4, h = bh & 15;
    const int d   = threadIdx.x & 63;
    const int sub = threadIdx.x >> 6;            // 0..3

    const __nv_bfloat16* kbase = kv + (size_t)b * SEQ * KVW + h * HD + d;
    const float* kwr   = kw + h * SEQ;
    const unsigned char* mrow = mask + b * SEQ;

    float s0 = 0.f, w0 = 0.f, s1 = 0.f, w1 = 0.f;
    const int n0 = chunk * 128 + sub * 32;
    #pragma unroll 4
    for (int n = n0; n < n0 + 32; n += 2) {
        float ka = __bfloat162float(kbase[(size_t)n * KVW]);
        float kb = __bfloat162float(kbase[(size_t)(n + 1) * KVW]);
        float xa = mrow[n]     ? -1e9f : ka * kwr[n]     * 0.125f;
        float xb = mrow[n + 1] ? -1e9f : kb * kwr[n + 1] * 0.125f;
        float ea = __expf(xa);
        float eb = __expf(xb);
        s0 += ea; w0 += ea * ka;
        s1 += eb; w1 += eb * kb;
    }
    float s = s0 + s1, w = w0 + w1;

    __shared__ float ss[4][64], sw[4][64];
    ss[sub][d] = s; sw[sub][d] = w;
    __syncthreads();
    if (sub == 0) {
        float S = ss[0][d] + ss[1][d] + ss[2][d] + ss[3][d];
        float W = sw[0][d] + sw[1][d] + sw[2][d] + sw[3][d];
        const size_t o = (size_t)blockIdx.x * HD + d;
        ps[o] = S; pw[o] = W;
    }
}

// gk phase 2: merge 8 chunk partials + divide. grid = 128, 64 thr.
__global__ void __launch_bounds__(64)
gk2_kernel(const float* __restrict__ ps, const float* __restrict__ pw,
           float* __restrict__ gk)
{
    const int bh = blockIdx.x;
    const int d  = threadIdx.x;
    const size_t base = (size_t)bh * 8 * HD + d;
    float S = 0.f, W = 0.f;
    #pragma unroll
    for (int c = 0; c < 8; c++) { S += ps[base + c * HD]; W += pw[base + c * HD]; }
    gk[(size_t)bh * HD + d] = W / S;
}

// ---------------------------------------------------------------------------
// prep: vgk = v(bf16, kv cols 1024..2047) * gk -> bf16
__global__ void __launch_bounds__(256)
prep_vgk(const __nv_bfloat16* __restrict__ kv, const float* __restrict__ gk,
         __nv_bfloat16* __restrict__ out)
{
    const int m = blockIdx.x;
    const int t = threadIdx.x;
    const uint2 vu = *reinterpret_cast<const uint2*>(&kv[(size_t)m * KVW + DM + t * 4]);
    const float2 v01 = __bfloat1622float2(*(const __nv_bfloat162*)&vu.x);
    const float2 v23 = __bfloat1622float2(*(const __nv_bfloat162*)&vu.y);
    const float4 gv = *reinterpret_cast<const float4*>(&gk[(size_t)(m >> 10) * DM + t * 4]);
    __nv_bfloat162 o01 = __floats2bfloat162_rn(v01.x * gv.x, v01.y * gv.y);
    __nv_bfloat162 o23 = __floats2bfloat162_rn(v23.x * gv.z, v23.y * gv.w);
    *reinterpret_cast<uint2*>(&out[(size_t)m * DM + t * 4]) =
        make_uint2(*(uint32_t*)&o01, *(uint32_t*)&o23);
}

// ---------------------------------------------------------------------------
// GEMM infrastructure. Plain GEMMs: BK=32, 5 stages (100 KB, 2 CTAs/SM).
// regl: BK=32, 4 stages + 32 KB hold (112 KB, 2 CTAs/SM).
#define ROWU   20                            // uint32 per smem row (80B)
#define STG_U  (256 * ROWU)
#define STG_B  (STG_U * 4)                   // 20480 bytes
#define P_STAGES 5
#define GEMM_SMEM (P_STAGES * STG_B)         // 102400 bytes
#define R_STAGES 4
#define RGL_PIPE (R_STAGES * STG_B)          // 81920
#define HOLD_U (R_STAGES * STG_U)
#define REGL_SMEM (RGL_PIPE + 64 * 128 * 4)  // 114688 bytes
#define GRIDP  296                           // 2 CTAs/SM * 148 SMs

__device__ __forceinline__ uint32_t stg5(int x) { return (uint32_t)(x % 5) * STG_B; }

// OMODE: 0 = fp32 out, 1 = bf16 out
// KSH = log2(ktiles per tile), TXSH = log2(tiles_x)
template<bool RES, int OMODE, int KSH, int TXSH>
__global__ void __launch_bounds__(128, 2)
mma_gemm_p(const __nv_bfloat16* __restrict__ A, const __nv_bfloat16* __restrict__ B,
           const float* __restrict__ bias, const float* __restrict__ res,
           void* __restrict__ Cv, int N, int lda, int ldb, int ntiles)
{
    extern __shared__ uint32_t smu[];
    const uint32_t sbase = smem_u32(smu);
    const int tid  = threadIdx.x;
    const int wid  = tid >> 5, lane = tid & 31;
    const int wm   = wid >> 1, wn = wid & 1;
    const int r    = lane >> 2, c = lane & 3;
    const int G    = gridDim.x;
    const int b0   = blockIdx.x;
    if (b0 >= ntiles) return;
    const int myTiles = (ntiles - 1 - b0) / G + 1;
    const int totc = myTiles << KSH;
    constexpr int ktm1 = (1 << KSH) - 1;
    constexpr int txm1 = (1 << TXSH) - 1;

    const int lrow = tid >> 2, lch = tid & 3;
    const uint32_t dA = sbase + (lrow * ROWU + lch * 4) * 4;
    const uint32_t dB = dA + 128 * ROWU * 4;

#define PRE(cc) do {                                                          \
        const int t_  = b0 + (((cc) >> KSH)) * G;                             \
        const int kt_ = (cc) & ktm1;                                          \
        const int nb_ = (t_ & txm1) << 7;                                     \
        const int mb_ = (t_ >> TXSH) << 7;                                    \
        const uint32_t so_ = stg5(cc);                                        \
        const __nv_bfloat16* pA = A + (size_t)(mb_ + lrow) * lda + kt_ * 32 + lch * 8; \
        const __nv_bfloat16* pB = B + (size_t)(nb_ + lrow) * ldb + kt_ * 32 + lch * 8; \
        _Pragma("unroll")                                                     \
        for (int j = 0; j < 4; j++) {                                         \
            CP16(dA + so_ + j * (32 * ROWU * 4), pA + (size_t)j * 32 * lda);  \
            CP16(dB + so_ + j * (32 * ROWU * 4), pB + (size_t)j * 32 * ldb);  \
        }                                                                     \
        CP_COMMIT();                                                          \
    } while (0)

    PRE(0); PRE(1); PRE(2); PRE(3);

    const int sub = lane >> 3, r8 = lane & 7;
    const int arow = wm * 64 + ((sub & 1) << 3) + r8;
    const uint32_t aaddr0 = sbase + (arow * ROWU + (sub >> 1) * 4) * 4;
    const int brow = wn * 64 + ((sub >> 1) << 3) + r8;
    const uint32_t baddr0 = sbase + 128 * ROWU * 4 + (brow * ROWU + (sub & 1) * 4) * 4;

    float acc[4][8][4] = {};

    for (int cc = 0; cc < totc; cc++) {
        CP_WAIT3();
        __syncthreads();
        if (cc + 4 < totc) PRE(cc + 4); else CP_COMMIT();   // keep group rhythm
        const uint32_t so = stg5(cc);

        #pragma unroll
        for (int ks = 0; ks < 2; ks++) {
            uint32_t af[4][4], bf[8][2];
            #pragma unroll
            for (int mt = 0; mt < 4; mt++)
                LDMX4(af[mt], aaddr0 + so + mt * (16 * ROWU * 4) + ks * 32);
            #pragma unroll
            for (int p = 0; p < 4; p++) {
                uint32_t t4[4];
                LDMX4(t4, baddr0 + so + p * (16 * ROWU * 4) + ks * 32);
                bf[2 * p][0] = t4[0]; bf[2 * p][1] = t4[1];
                bf[2 * p + 1][0] = t4[2]; bf[2 * p + 1][1] = t4[3];
            }
            #pragma unroll
            for (int mt = 0; mt < 4; mt++)
                #pragma unroll
                for (int nt = 0; nt < 8; nt++)
                    mma16(acc[mt][nt], af[mt], bf[nt]);
        }

        if ((cc & ktm1) == ktm1) {
            const int tile  = b0 + (cc >> KSH) * G;
            const int nbase = (tile & txm1) << 7;
            const int mbase = (tile >> TXSH) << 7;
            #pragma unroll
            for (int nt = 0; nt < 8; nt++) {
                const int col = nbase + wn * 64 + nt * 8 + 2 * c;
                const float2 bv = *reinterpret_cast<const float2*>(&bias[col]);
                #pragma unroll
                for (int mt = 0; mt < 4; mt++) {
                    const int row = mbase + wm * 64 + mt * 16 + r;
                    float2 o0, o1;
                    o0.x = acc[mt][nt][0] + bv.x; o0.y = acc[mt][nt][1] + bv.y;
                    o1.x = acc[mt][nt][2] + bv.x; o1.y = acc[mt][nt][3] + bv.y;
                    if (RES) {
                        const float2 r0 = *reinterpret_cast<const float2*>(&res[(size_t)row * N + col]);
                        const float2 r1 = *reinterpret_cast<const float2*>(&res[(size_t)(row + 8) * N + col]);
                        o0.x += r0.x; o0.y += r0.y;
                        o1.x += r1.x; o1.y += r1.y;
                    }
                    if (OMODE == 1) {
                        __nv_bfloat16* Cb = (__nv_bfloat16*)Cv;
                        __nv_bfloat162 p0 = __floats2bfloat162_rn(o0.x, o0.y);
                        __nv_bfloat162 p1 = __floats2bfloat162_rn(o1.x, o1.y);
                        *reinterpret_cast<uint32_t*>(&Cb[(size_t)row * N + col])       = *(uint32_t*)&p0;
                        *reinterpret_cast<uint32_t*>(&Cb[(size_t)(row + 8) * N + col]) = *(uint32_t*)&p1;
                    } else {
                        float* Cf = (float*)Cv;
                        *reinterpret_cast<float2*>(&Cf[(size_t)row * N + col])       = o0;
                        *reinterpret_cast<float2*>(&Cf[(size_t)(row + 8) * N + col]) = o1;
                    }
                    acc[mt][nt][0] = acc[mt][nt][1] = acc[mt][nt][2] = acc[mt][nt][3] = 0.f;
                }
            }
        }
    }
#undef PRE
}

// ---------------------------------------------------------------------------
// persistent fused ff1 + ReGLU (round-13 verbatim). 64 chunks per tile,
// tiles_x=16; 'a' spilled to smem hold at kt==31, combined at kt==63.
__global__ void __launch_bounds__(128, 2)
regl_gemm_p(const __nv_bfloat16* __restrict__ A, const __nv_bfloat16* __restrict__ B,
            const float* __restrict__ bias, __nv_bfloat16* __restrict__ gate,
            int ntiles)
{
    extern __shared__ uint32_t smu[];
    const uint32_t sbase = smem_u32(smu);
    const int tid  = threadIdx.x;
    const int wid  = tid >> 5, lane = tid & 31;
    const int wm   = wid >> 1, wn = wid & 1;
    const int r    = lane >> 2, c = lane & 3;
    const int G    = gridDim.x;
    const int b0   = blockIdx.x;
    if (b0 >= ntiles) return;
    const int myTiles = (ntiles - 1 - b0) / G + 1;
    const int totc = myTiles << 6;

    const int lrow = tid >> 2, lch = tid & 3;
    const uint32_t dA = sbase + (lrow * ROWU + lch * 4) * 4;
    const uint32_t dB = dA + 128 * ROWU * 4;

#define PRE(cc) do {                                                          \
        const int t_  = b0 + (((cc) >> 6)) * G;                               \
        const int kt_ = (cc) & 63;                                            \
        const int nb_ = (t_ & 15) << 7;                                       \
        const int mb_ = (t_ >> 4) << 7;                                       \
        const int k0_ = (kt_ & 31) * 32;                                      \
        const uint32_t so_ = ((cc) & 3) * STG_B;                              \
        const __nv_bfloat16* pA = A + (size_t)(mb_ + lrow) * DM + k0_ + lch * 8; \
        const __nv_bfloat16* pB = B + (size_t)(nb_ + lrow + ((kt_ >> 5) ? 2048 : 0)) * DM + k0_ + lch * 8; \
        _Pragma("unroll")                                                     \
        for (int j = 0; j < 4; j++) {                                         \
            CP16(dA + so_ + j * (32 * ROWU * 4), pA + (size_t)j * 32 * DM);   \
            CP16(dB + so_ + j * (32 * ROWU * 4), pB + (size_t)j * 32 * DM);   \
        }                                                                     \
        CP_COMMIT();                                                          \
    } while (0)

    PRE(0); PRE(1); PRE(2);

    const int sub = lane >> 3, r8 = lane & 7;
    const int arow = wm * 64 + ((sub & 1) << 3) + r8;
    const uint32_t aaddr0 = sbase + (arow * ROWU + (sub >> 1) * 4) * 4;
    const int brow = wn * 64 + ((sub >> 1) << 3) + r8;
    const uint32_t baddr0 = sbase + 128 * ROWU * 4 + (brow * ROWU + (sub & 1) * 4) * 4;

    float acc[4][8][4] = {};

    for (int cc = 0; cc < totc; cc++) {
        CP_WAIT2();
        __syncthreads();
        if (cc + 3 < totc) PRE(cc + 3); else CP_COMMIT();
        const uint32_t so = (cc & 3) * STG_B;

        #pragma unroll
        for (int ks = 0; ks < 2; ks++) {
            uint32_t af[4][4], bf[8][2];
            #pragma unroll
            for (int mt = 0; mt < 4; mt++)
                LDMX4(af[mt], aaddr0 + so + mt * (16 * ROWU * 4) + ks * 32);
            #pragma unroll
            for (int p = 0; p < 4; p++) {
                uint32_t t4[4];
                LDMX4(t4, baddr0 + so + p * (16 * ROWU * 4) + ks * 32);
                bf[2 * p][0] = t4[0]; bf[2 * p][1] = t4[1];
                bf[2 * p + 1][0] = t4[2]; bf[2 * p + 1][1] = t4[3];
            }
            #pragma unroll
            for (int mt = 0; mt < 4; mt++)
                #pragma unroll
                for (int nt = 0; nt < 8; nt++)
                    mma16(acc[mt][nt], af[mt], bf[nt]);
        }

        const int kt = cc & 63;
        if (kt == 31) {
            const int tile  = b0 + (cc >> 6) * G;
            const int nbase = (tile & 15) << 7;
            #pragma unroll
            for (int nt = 0; nt < 8; nt++) {
                const int col = nbase + wn * 64 + nt * 8 + 2 * c;
                const float2 bv = *reinterpret_cast<const float2*>(&bias[col]);
                #pragma unroll
                for (int mt = 0; mt < 4; mt++) {
                    __nv_bfloat162 p0 = __floats2bfloat162_rn(acc[mt][nt][0] + bv.x,
                                                              acc[mt][nt][1] + bv.y);
                    __nv_bfloat162 p1 = __floats2bfloat162_rn(acc[mt][nt][2] + bv.x,
                                                              acc[mt][nt][3] + bv.y);
                    const int slot = (nt * 4 + mt) * 2;
                    smu[HOLD_U + slot * 128 + tid]       = *(uint32_t*)&p0;
                    smu[HOLD_U + (slot + 1) * 128 + tid] = *(uint32_t*)&p1;
                    acc[mt][nt][0] = acc[mt][nt][1] = acc[mt][nt][2] = acc[mt][nt][3] = 0.f;
                }
            }
        } else if (kt == 63) {
            const int tile  = b0 + (cc >> 6) * G;
            const int nbase = (tile & 15) << 7;
            const int mbase = (tile >> 4) << 7;
            #pragma unroll
            for (int nt = 0; nt < 8; nt++) {
                const int col = nbase + wn * 64 + nt * 8 + 2 * c;
                const float2 bg = *reinterpret_cast<const float2*>(&bias[2048 + col]);
                #pragma unroll
                for (int mt = 0; mt < 4; mt++) {
                    const int row = mbase + wm * 64 + mt * 16 + r;
                    const float g0x = fmaxf(acc[mt][nt][0] + bg.x, 0.f);
                    const float g0y = fmaxf(acc[mt][nt][1] + bg.y, 0.f);
                    const float g1x = fmaxf(acc[mt][nt][2] + bg.x, 0.f);
                    const float g1y = fmaxf(acc[mt][nt][3] + bg.y, 0.f);
                    const int slot = (nt * 4 + mt) * 2;
                    const uint32_t a0 = smu[HOLD_U + slot * 128 + tid];
                    const uint32_t a1 = smu[HOLD_U + (slot + 1) * 128 + tid];
                    const float2 af0 = __bfloat1622float2(*(const __nv_bfloat162*)&a0);
                    const float2 af1 = __bfloat1622float2(*(const __nv_bfloat162*)&a1);
                    __nv_bfloat162 p0 = __floats2bfloat162_rn(af0.x * g0x, af0.y * g0y);
                    __nv_bfloat162 p1 = __floats2bfloat162_rn(af1.x * g1x, af1.y * g1y);
                    *reinterpret_cast<uint32_t*>(&gate[(size_t)row * 2048 + col])       = *(uint32_t*)&p0;
                    *reinterpret_cast<uint32_t*>(&gate[(size_t)(row + 8) * 2048 + col]) = *(uint32_t*)&p1;
                    acc[mt][nt][0] = acc[mt][nt][1] = acc[mt][nt][2] = acc[mt][nt][3] = 0.f;
                }
            }
        }
    }
#undef PRE
}

// ---------------------------------------------------------------------------
extern "C" void kernel_launch(void* const* d_in, const int* in_sizes, int n_in,
                              void* d_out, int out_size)
{
    const float*         hidden = (const float*)d_in[0];
    const unsigned char* mask   = (const unsigned char*)d_in[1];
    const float*         qkv_w  = (const float*)d_in[2];
    const float*         qkv_b  = (const float*)d_in[3];
    const float*         out_w  = (const float*)d_in[4];
    const float*         out_b  = (const float*)d_in[5];
    const float*         key_w  = (const float*)d_in[7];
    const float*         n1g    = (const float*)d_in[8];
    const float*         n1b    = (const float*)d_in[9];
    const float*         n2g    = (const float*)d_in[10];
    const float*         n2b    = (const float*)d_in[11];
    const float*         l1w    = (const float*)d_in[12];
    const float*         l1b    = (const float*)d_in[13];
    const float*         l2w    = (const float*)d_in[14];
    const float*         l2b    = (const float*)d_in[15];
    float* out = (float*)d_out;

    __nv_bfloat16 *h, *kvb, *vgk, *gate, *w1, *w2, *w3, *w4;
    float *gk, *ps, *pw, *hid2;
    cudaGetSymbolAddress((void**)&h,    g_h);
    cudaGetSymbolAddress((void**)&kvb,  g_kv);
    cudaGetSymbolAddress((void**)&gk,   g_gk);
    cudaGetSymbolAddress((void**)&ps,   g_ps);
    cudaGetSymbolAddress((void**)&pw,   g_pw);
    cudaGetSymbolAddress((void**)&hid2, g_hid2);
    cudaGetSymbolAddress((void**)&vgk,  g_vgk);
    cudaGetSymbolAddress((void**)&gate, g_gate);
    cudaGetSymbolAddress((void**)&w1,   g_w1);
    cudaGetSymbolAddress((void**)&w2,   g_w2);
    cudaGetSymbolAddress((void**)&w3,   g_w3);
    cudaGetSymbolAddress((void**)&w4,   g_w4);

    cudaFuncSetAttribute((const void*)mma_gemm_p<false,1,5,4>, cudaFuncAttributeMaxDynamicSharedMemorySize, GEMM_SMEM);
    cudaFuncSetAttribute((const void*)mma_gemm_p<true,0,5,3>,  cudaFuncAttributeMaxDynamicSharedMemorySize, GEMM_SMEM);
    cudaFuncSetAttribute((const void*)mma_gemm_p<true,0,6,3>,  cudaFuncAttributeMaxDynamicSharedMemorySize, GEMM_SMEM);
    cudaFuncSetAttribute((const void*)regl_gemm_p,             cudaFuncAttributeMaxDynamicSharedMemorySize, REGL_SMEM);

    // 1) w1 conversion (kv GEMM dependency)
    cvt_w1<<<262144 / 256, 256>>>((const float4*)qkv_w, w1);

    // 2) rest of weights
    cvt_rest<<<(R3 + 255) / 256, 256>>>((const float4*)out_w, (const float4*)l1w,
                                        (const float4*)l2w, w2, w3, w4);

    // 3) LN1
    ln_kernel<<<ROWS / 8, 256>>>(hidden, n1g, n1b, h);

    // 4) kv GEMM (persistent, bf16 out).  16x64 = 1024 tiles.  [ncu-captured]
    mma_gemm_p<false,1,5,4><<<GRIDP, 128, GEMM_SMEM>>>(
        h, w1, qkv_b + DM, nullptr, kvb, KVW, DM, DM, 1024);

    // 5) gk phase 1 (no-max, bf16 k)
    gk1_kernel<<<BATCH * NH * 8, 256>>>(kvb, key_w, mask, ps, pw);

    // 6) gk phase 2
    gk2_kernel<<<BATCH * NH, 64>>>(ps, pw, gk);

    // 7) vgk = v * gk
    prep_vgk<<<ROWS, 256>>>(kvb, gk, vgk);

    // 8) hid2 = vgk @ out_w^T + out_b + hidden.  8x64 = 512 tiles.
    mma_gemm_p<true,0,5,3><<<GRIDP, 128, GEMM_SMEM>>>(
        vgk, w2, out_b, hidden, hid2, DM, DM, DM, 512);

    // 9) LN2
    ln_kernel<<<ROWS / 8, 256>>>(hid2, n2g, n2b, h);

    // 10) gate = (h@w3a^T+ba) * relu(h@w3g^T+bg).  16x64 = 1024 tiles.
    regl_gemm_p<<<GRIDP, 128, REGL_SMEM>>>(h, w3, l1b, gate, 1024);

    // 11) out = gate @ lin2_w^T + lin2_b + hid2.  8x64 = 512 tiles, K=2048.
    mma_gemm_p<true,0,6,3><<<GRIDP, 128, GEMM_SMEM>>>(
        gate, w4, l2b, hid2, out, DM, FF / 2, FF / 2, 512);
}